// round 16
// baseline (speedup 1.0000x reference)
#include <cuda_runtime.h>
#include <cuda_fp16.h>
#include <stdint.h>
#include <math.h>

#define B_ 64
#define N_ 4096
#define V_ 21
#define S_ 50
#define E_ 64
#define H_ 128
#define THREADS 512
#define GTHREADS 128
#define NGRP 4
#define NCTAS 148
#define PADH 136      // halves per padded smem row (272B)

#define NT0 22050     // 21*21*50 unique (tokL, tokR, symbol) leaf-pair triples
#define NPAIR 441     // 21*21 unique (tokL, tokR) pairs
#define PTILES 28     // ceil(441/16)

// smem layout (bytes)
#define SMU_BYTES (512*PADH*2)   // 139264: U-concat
#define HL16 4352                // 16 rows x 272B
#define BUF16 (2*HL16)           // 8704: HL+HR for one 16-row tile
#define SM_TOTAL (SMU_BYTES + NGRP*2*BUF16)   // 208896

// deep-phase layout inside the buffer region (offsets from SMU_BYTES)
#define DP_H    0        // 64 rows x 256B fp16
#define DP_C    16384    // 64 rows x 512B fp32
#define DP_A    49152    // HL 32x272 = 8704, HR 8704
#define DP_ROOT 66560    // 128 floats

// ---------------- static device scratch ----------------
__device__ float4 g_tab4[S_*H_];        // per-symbol gate tables: {ai, ao, au, af}
__device__ float4 g_P4[NPAIR*H_];       // per-pair preacts: {pi, po, pu, fl}
__device__ float  g_Pfr[NPAIR*H_];      // per-pair preacts: fr
__device__ __half g_h016[V_*H_];
__device__ float  g_c0[V_*H_];
__device__ __half g_Hm[22080*H_];       // memo: level-0 h by triple index
__device__ float  g_Cm[22080*H_];
__device__ __half g_HA[B_*1024*H_];     // lvl1,3 outputs
__device__ float  g_CA[B_*1024*H_];
__device__ __half g_HB[B_*512*H_];      // lvl2,4 outputs
__device__ float  g_CB[B_*512*H_];
__device__ unsigned g_tick[4];          // work-stealing counters lvl1..3
__device__ unsigned g_bar;
__device__ unsigned g_done;

__device__ __forceinline__ float tha(float x){
  float y; asm("tanh.approx.f32 %0, %1;" : "=f"(y) : "f"(x)); return y;
}
__device__ __forceinline__ float sga(float x){ return 0.5f*tha(0.5f*x) + 0.5f; }

__device__ __forceinline__ unsigned saddr(const void* p){
  return (unsigned)__cvta_generic_to_shared(p);
}
__device__ __forceinline__ void ldsm4(unsigned addr, unsigned &r0, unsigned &r1, unsigned &r2, unsigned &r3){
  asm volatile("ldmatrix.sync.aligned.m8n8.x4.shared.b16 {%0,%1,%2,%3}, [%4];"
    : "=r"(r0),"=r"(r1),"=r"(r2),"=r"(r3) : "r"(addr));
}
__device__ __forceinline__ void mma16816(float d[4], const unsigned a[4], unsigned b0, unsigned b1){
  asm volatile("mma.sync.aligned.m16n8k16.row.col.f32.f16.f16.f32 "
    "{%0,%1,%2,%3}, {%4,%5,%6,%7}, {%8,%9}, {%0,%1,%2,%3};"
    : "+f"(d[0]),"+f"(d[1]),"+f"(d[2]),"+f"(d[3])
    : "r"(a[0]),"r"(a[1]),"r"(a[2]),"r"(a[3]), "r"(b0),"r"(b1));
}
__device__ __forceinline__ uint32_t hadd2u(uint32_t a, uint32_t b){
  __half2 r = __hadd2(*reinterpret_cast<__half2*>(&a), *reinterpret_cast<__half2*>(&b));
  return *reinterpret_cast<uint32_t*>(&r);
}
__device__ __forceinline__ uint4 ldcg4(const uint4* p){
  uint4 v;
  asm volatile("ld.global.cg.v4.u32 {%0,%1,%2,%3}, [%4];"
    : "=r"(v.x),"=r"(v.y),"=r"(v.z),"=r"(v.w) : "l"(p));
  return v;
}
__device__ __forceinline__ float2 ldcg2f(const float2* p){
  float2 v;
  asm volatile("ld.global.cg.v2.f32 {%0,%1}, [%2];" : "=f"(v.x),"=f"(v.y) : "l"(p));
  return v;
}
__device__ __forceinline__ void stcg2f(float2* p, float2 v){
  asm volatile("st.global.cg.v2.f32 [%0], {%1,%2};" :: "l"(p), "f"(v.x), "f"(v.y) : "memory");
}
__device__ __forceinline__ void stcgu(uint32_t* p, uint32_t v){
  asm volatile("st.global.cg.u32 [%0], %1;" :: "l"(p), "r"(v) : "memory");
}
__device__ __forceinline__ void cpa16(uint32_t dst, const void* src){
  asm volatile("cp.async.cg.shared.global [%0], [%1], 16;" :: "r"(dst), "l"(src) : "memory");
}
#define CP_COMMIT asm volatile("cp.async.commit_group;" ::: "memory")
#define CP_WAIT0  asm volatile("cp.async.wait_group 0;" ::: "memory")

// memo indices for BOTH children of lvl1 node (b, j): one int4 token load + 2 symbol loads.
// tokens + b*N_ + 4*j is 16B-aligned (N_ and 4*j are multiples of 4).
__device__ __forceinline__ int2 memo_idx2(const int* __restrict__ tokens,
                                          const int* __restrict__ symbols, int b, int j){
  int4 t = __ldg((const int4*)(tokens + b*N_ + 4*j));
  int s0 = __ldg(&symbols[b*(N_-1) + 2*j]);
  int s1 = __ldg(&symbols[b*(N_-1) + 2*j + 1]);
  return make_int2((t.x*V_ + t.y)*S_ + s0, (t.z*V_ + t.w)*S_ + s1);
}

// ---------------- GEMM tile: 16 (or 32 deep) rows x 128 cols, 5 gate-products ----------------
__device__ __forceinline__ void gemm_tile(const __half* sU, const __half* sHL, const __half* sHR,
                                          int lane, int wm, int wn,
                                          float acc1[12][4], float acc2[8][4]){
  #pragma unroll
  for (int i = 0; i < 12; i++){ acc1[i][0]=0.f; acc1[i][1]=0.f; acc1[i][2]=0.f; acc1[i][3]=0.f; }
  #pragma unroll
  for (int i = 0; i < 8; i++){ acc2[i][0]=0.f; acc2[i][1]=0.f; acc2[i][2]=0.f; acc2[i][3]=0.f; }
  #pragma unroll
  for (int k16 = 0; k16 < 8; k16++){
    const int kh = k16*16;
    const int arow = 16*wm + (lane & 15);
    const int acol = kh + (lane >> 4)*8;
    unsigned aL[4], aR[4], aT[4];
    ldsm4(saddr(&sHL[arow*PADH + acol]), aL[0],aL[1],aL[2],aL[3]);
    ldsm4(saddr(&sHR[arow*PADH + acol]), aR[0],aR[1],aR[2],aR[3]);
    #pragma unroll
    for (int i = 0; i < 4; i++) aT[i] = hadd2u(aL[i], aR[i]);   // ht = hl + hr

    const int brow_in = ((lane>>4)&1)*8 + (lane&7);
    const int bcol    = kh + ((lane>>3)&1)*8;
    #pragma unroll
    for (int gg = 0; gg < 3; gg++){
      #pragma unroll
      for (int sp = 0; sp < 2; sp++){
        int R0 = 128*gg + 32*wn + 16*sp;
        unsigned r0,r1,r2,r3;
        ldsm4(saddr(&sU[(R0 + brow_in)*PADH + bcol]), r0,r1,r2,r3);
        mma16816(acc1[gg*4 + 2*sp + 0], aT, r0, r1);
        mma16816(acc1[gg*4 + 2*sp + 1], aT, r2, r3);
      }
    }
    #pragma unroll
    for (int sp = 0; sp < 2; sp++){
      int R0 = 384 + 32*wn + 16*sp;
      unsigned r0,r1,r2,r3;
      ldsm4(saddr(&sU[(R0 + brow_in)*PADH + bcol]), r0,r1,r2,r3);
      mma16816(acc2[2*sp + 0], aL, r0, r1);
      mma16816(acc2[2*sp + 1], aL, r2, r3);
      mma16816(acc2[4 + 2*sp + 0], aR, r0, r1);
      mma16816(acc2[4 + 2*sp + 1], aR, r2, r3);
    }
  }
}

// async-stage 16-node tile. lvl==0: pair mode (i0 = p/21, i1 = p%21).
__device__ __forceinline__ void stage16(char* bufbase, const __half* Hsrc,
    const int* __restrict__ tokens, const int* __restrict__ symbols,
    int lvl, int node0, int logm, int m, int total, int ltid){
  const char* Hb = (const char*)Hsrc;
  uint32_t sHL = saddr(bufbase);
  uint32_t sHR = sHL + HL16;
  #pragma unroll
  for (int it = 0; it < 2; it++){
    int idx = ltid + it*GTHREADS;     // 0..255
    int r = idx >> 4, q = idx & 15;
    int n_g = node0 + r;
    int i0 = 0, i1 = 0;
    if (n_g < total){
      if (lvl == 0){
        i0 = n_g/V_;
        i1 = n_g - i0*V_;
      } else if (lvl == 1){
        int b = n_g >> logm, j = n_g & (m-1);
        int2 ii = memo_idx2(tokens, symbols, b, j);
        i0 = ii.x; i1 = ii.y;
      } else { i0 = 2*n_g; i1 = 2*n_g + 1; }
    }
    int boff = r*(PADH*2) + q*16;
    cpa16(sHL + boff, Hb + (size_t)i0*256 + q*16);
    cpa16(sHR + boff, Hb + (size_t)i1*256 + q*16);
  }
  CP_COMMIT;
}

// gate math for one column pair given fused table entries
__device__ __forceinline__ void gate2(
    float pi0, float pi1, float po0, float po1, float pu0, float pu1,
    float fl0, float fl1, float fr0, float fr1,
    float2 cl, float2 cr, float2 &cn, float2 &hn){
  cn.x = sga(pi0)*tha(pu0) + sga(fl0)*cl.x + sga(fr0)*cr.x;
  cn.y = sga(pi1)*tha(pu1) + sga(fl1)*cl.y + sga(fr1)*cr.y;
  hn.x = sga(po0)*tha(cn.x);
  hn.y = sga(po1)*tha(cn.y);
}

// epilogue for levels 1..4 (16-row tiles, wm = 0; all rows valid)
__device__ __forceinline__ void epilogue_15(
    const float acc1[12][4], const float acc2[8][4],
    int lvl, int node0, int off, int m, int logm,
    const float* Csrc, __half* Hdst, float* Cdst,
    const int* __restrict__ tokens, const int* __restrict__ symbols,
    int lane, int wm, int wn){
  #pragma unroll
  for (int half = 0; half < 2; half++){
    int nl = 16*wm + (lane >> 2) + 8*half;
    int n_g = node0 + nl;
    int b = n_g >> logm, j = n_g & (m-1);
    int sym = __ldg(&symbols[b*(N_-1) + off + j]);
    int i0, i1;
    if (lvl == 1){
      int2 ii = memo_idx2(tokens, symbols, b, j);
      i0 = ii.x; i1 = ii.y;
    } else { i0 = 2*n_g; i1 = 2*n_g + 1; }
    const float2* cl2p = (const float2*)(Csrc + (size_t)i0*H_);
    const float2* cr2p = (const float2*)(Csrc + (size_t)i1*H_);
    const float4* tab  = (const float4*)(g_tab4 + sym*H_);
    float2*  co = (float2*)(Cdst + (size_t)n_g*H_);
    uint32_t* ho = (uint32_t*)(Hdst + (size_t)n_g*H_);
    const int e = 2*half;
    float2 cl[4], cr[4];
    #pragma unroll
    for (int s = 0; s < 4; s++){
      int c2 = 16*wn + 4*s + (lane & 3);
      cl[s] = ldcg2f(cl2p + c2);
      cr[s] = ldcg2f(cr2p + c2);
    }
    #pragma unroll
    for (int s = 0; s < 4; s++){
      int c2 = 16*wn + 4*s + (lane & 3);
      float4 t0 = __ldg(tab + 2*c2);
      float4 t1 = __ldg(tab + 2*c2 + 1);
      float2 cn, hn;
      gate2(acc1[0*4+s][e] + t0.x, acc1[0*4+s][e+1] + t1.x,
            acc1[1*4+s][e] + t0.y, acc1[1*4+s][e+1] + t1.y,
            acc1[2*4+s][e] + t0.z, acc1[2*4+s][e+1] + t1.z,
            acc2[s][e]     + t0.w, acc2[s][e+1]     + t1.w,
            acc2[4+s][e]   + t0.w, acc2[4+s][e+1]   + t1.w,
            cl[s], cr[s], cn, hn);
      stcg2f(co + c2, cn);
      __half2 hh = __floats2half2_rn(hn.x, hn.y);
      stcgu(ho + c2, *reinterpret_cast<uint32_t*>(&hh));
    }
  }
}

// ---------------- fused persistent kernel ----------------
extern __shared__ char smx[];
__global__ __launch_bounds__(THREADS, 1) void fused_kernel(
  const int* __restrict__ tokens, const int* __restrict__ symbols,
  const float* __restrict__ emb, const float* __restrict__ sym_emb,
  const float* __restrict__ Wp, const float* __restrict__ bp,
  const float* __restrict__ Wi, const float* __restrict__ bi,
  const float* __restrict__ Ui, const float* __restrict__ Wf,
  const float* __restrict__ bf, const float* __restrict__ Uf,
  const float* __restrict__ Wo, const float* __restrict__ bo,
  const float* __restrict__ Uo, const float* __restrict__ Wu,
  const float* __restrict__ bu, const float* __restrict__ Uu,
  const float* __restrict__ Wout, const float* __restrict__ bout,
  float* __restrict__ out)
{
  const int tid = threadIdx.x;
  const int lane = tid & 31, wid = tid >> 5;
  const int grp = tid >> 7;               // 0..3: independent quarter-CTA pipeline
  const int ltid = tid & 127;
  const int wn = wid & 3;                 // 32-col group
  const int wmD = wid >> 2;               // deep-phase row group (0..3)
  __half* sU = (__half*)smx;
  __shared__ int sTick[NGRP];

  #define GBAR() asm volatile("bar.sync %0, %1;" :: "r"(1 + grp), "r"(GTHREADS) : "memory")

  // ---- phase 0: stage fp16 U-concat into smem ----
  for (int idx = tid; idx < 512*32; idx += THREADS){
    int r = idx >> 5, q = idx & 31;
    const float* src = (r < 128) ? Ui + r*H_
                      : (r < 256) ? Uo + (r-128)*H_
                      : (r < 384) ? Uu + (r-256)*H_
                      :             Uf + (r-384)*H_;
    float4 v = __ldg((const float4*)src + q);
    __half2 h0 = __floats2half2_rn(v.x, v.y);
    __half2 h1 = __floats2half2_rn(v.z, v.w);
    uint2 u;
    u.x = *reinterpret_cast<uint32_t*>(&h0);
    u.y = *reinterpret_cast<uint32_t*>(&h1);
    *(uint2*)(smx + (r*PADH + q*4)*2) = u;
  }

  // ---- phase 0b: leaf/symbol tables ----
  if (blockIdx.x < V_ + S_){
    float* se = (float*)(smx + SMU_BYTES);
    float* sx = se + E_;
    const int v_or_s = blockIdx.x;
    const int h = tid;
    if (tid < E_)
      se[tid] = (v_or_s < V_) ? emb[v_or_s*E_ + tid] : sym_emb[(v_or_s - V_)*E_ + tid];
    __syncthreads();
    if (tid < H_){
      float x = bp[h];
      #pragma unroll 8
      for (int e = 0; e < E_; e++) x += se[e]*Wp[h*E_ + e];
      sx[h] = x;
    }
    __syncthreads();
    if (tid < H_){
      if (v_or_s < V_){
        float ai_ = bi[h], ao_ = bo[h], au_ = bu[h];
        #pragma unroll 8
        for (int k = 0; k < H_; k++){
          float xv = sx[k];
          ai_ += xv*Wi[h*H_+k]; ao_ += xv*Wo[h*H_+k]; au_ += xv*Wu[h*H_+k];
        }
        float gi = 1.f/(1.f+expf(-ai_)), go = 1.f/(1.f+expf(-ao_)), gu = tanhf(au_);
        float c = gi*gu;
        g_c0[v_or_s*H_+h] = c;
        g_h016[v_or_s*H_+h] = __float2half(go*tanhf(c));
      } else {
        int s = v_or_s - V_;
        float ai_ = bi[h], ao_ = bo[h], au_ = bu[h], af_ = bf[h];
        #pragma unroll 8
        for (int k = 0; k < H_; k++){
          float xv = sx[k];
          ai_ += xv*Wi[h*H_+k]; ao_ += xv*Wo[h*H_+k];
          au_ += xv*Wu[h*H_+k]; af_ += xv*Wf[h*H_+k];
        }
        g_tab4[s*H_+h] = make_float4(ai_, ao_, au_, af_);
      }
    }
  }

  unsigned ep = 0;
  #define GRID_BAR() do { \
    ep++; \
    __syncthreads(); \
    if (tid == 0){ \
      __threadfence(); \
      atomicAdd(&g_bar, 1u); \
      const unsigned tgt = ep*NCTAS; \
      while (*(volatile unsigned*)&g_bar < tgt) __nanosleep(32); \
      __threadfence(); \
    } \
    __syncthreads(); \
  } while(0)

  GRID_BAR();   // tables + U ready

  char* gb0 = smx + SMU_BYTES + grp*(2*BUF16);
  char* gb1 = gb0 + BUF16;

  // =========== phase P: pair preacts for 441 (tokL, tokR) pairs ===========
  {
    const int t = NGRP*(int)blockIdx.x + grp;
    if (t < PTILES){
      stage16(gb0, g_h016, tokens, symbols, 0, t << 4, 0, 0, NPAIR, ltid);
      CP_WAIT0;
      GBAR();
      float acc1[12][4], acc2[8][4];
      gemm_tile(sU, (const __half*)gb0, (const __half*)(gb0 + HL16), lane, 0, wn, acc1, acc2);
      #pragma unroll
      for (int half = 0; half < 2; half++){
        int nl = (lane >> 2) + 8*half;
        int p = (t << 4) + nl;
        if (p < NPAIR){
          const int e = 2*half;
          float4* P4 = g_P4 + (size_t)p*H_;
          float*  Pf = g_Pfr + (size_t)p*H_;
          #pragma unroll
          for (int s = 0; s < 4; s++){
            int c2 = 16*wn + 4*s + (lane & 3);
            P4[2*c2]   = make_float4(acc1[0*4+s][e],   acc1[1*4+s][e],   acc1[2*4+s][e],   acc2[s][e]);
            P4[2*c2+1] = make_float4(acc1[0*4+s][e+1], acc1[1*4+s][e+1], acc1[2*4+s][e+1], acc2[s][e+1]);
            Pf[2*c2]   = acc2[4+s][e];
            Pf[2*c2+1] = acc2[4+s][e+1];
          }
        }
      }
    }
  }
  GRID_BAR();

  // =========== phase M: memo elementwise over 22050 triples ===========
  {
    const float2* C02 = (const float2*)g_c0;
    for (int idx = (int)blockIdx.x*THREADS + tid; idx < NT0*64; idx += NCTAS*THREADS){
      int g = idx >> 6, cp = idx & 63;
      int ta = g/(V_*S_);
      int rem = g - ta*(V_*S_);
      int tb = rem/S_;
      int s  = rem - tb*S_;
      int pair = ta*V_ + tb;
      const float4* P4 = g_P4 + (size_t)pair*H_ + 2*cp;
      float4 a0 = __ldg(P4), a1 = __ldg(P4 + 1);
      float fr0 = __ldg(g_Pfr + (size_t)pair*H_ + 2*cp);
      float fr1 = __ldg(g_Pfr + (size_t)pair*H_ + 2*cp + 1);
      const float4* T4 = g_tab4 + (size_t)s*H_ + 2*cp;
      float4 t0 = __ldg(T4), t1 = __ldg(T4 + 1);
      float2 cl = __ldg(C02 + ta*64 + cp);
      float2 cr = __ldg(C02 + tb*64 + cp);
      float2 cn, hn;
      gate2(a0.x + t0.x, a1.x + t1.x,
            a0.y + t0.y, a1.y + t1.y,
            a0.z + t0.z, a1.z + t1.z,
            a0.w + t0.w, a1.w + t1.w,
            fr0 + t0.w,  fr1 + t1.w,
            cl, cr, cn, hn);
      stcg2f((float2*)g_Cm + (size_t)g*64 + cp, cn);
      __half2 hh = __floats2half2_rn(hn.x, hn.y);
      stcgu((uint32_t*)g_Hm + (size_t)g*64 + cp, *reinterpret_cast<uint32_t*>(&hh));
    }
  }
  GRID_BAR();

  // =========== levels 1..5 (m = 1024..64) ===========
  int m = 1024, off = 2048;
  for (int lvl = 1; lvl < 6; lvl++){
    const __half* Hsrc; const float* Csrc;
    __half* Hdst; float* Cdst;
    if (lvl == 1)      { Hsrc = g_Hm; Csrc = g_Cm; }
    else if (lvl & 1)  { Hsrc = g_HB; Csrc = g_CB; }
    else               { Hsrc = g_HA; Csrc = g_CA; }
    if (lvl & 1) { Hdst = g_HA; Cdst = g_CA; } else { Hdst = g_HB; Cdst = g_CB; }

    const int tiles = (B_*m) >> 4;
    const int logm  = 31 - __clz(m);
    const int total = B_*m;

    if (lvl <= 3){
      // ---- per-group work stealing ----
      if (ltid == 0) sTick[grp] = (int)atomicAdd(&g_tick[lvl], 1u);
      GBAR();
      int t = sTick[grp];
      int buf = 0;
      if (t < tiles)
        stage16(gb0, Hsrc, tokens, symbols, lvl, t << 4, logm, m, total, ltid);
      if (ltid == 0) sTick[grp] = (int)atomicAdd(&g_tick[lvl], 1u);
      CP_WAIT0;
      GBAR();
      int tn = sTick[grp];

      while (t < tiles){
        char* bb = buf ? gb1 : gb0;
        char* nb = buf ? gb0 : gb1;

        if (tn < tiles)
          stage16(nb, Hsrc, tokens, symbols, lvl, tn << 4, logm, m, total, ltid);

        float acc1[12][4], acc2[8][4];
        gemm_tile(sU, (const __half*)bb, (const __half*)(bb + HL16), lane, 0, wn, acc1, acc2);

        epilogue_15(acc1, acc2, lvl, t << 4, off, m, logm, Csrc, Hdst, Cdst,
                    tokens, symbols, lane, 0, wn);

        if (ltid == 0 && tn < tiles) sTick[grp] = (int)atomicAdd(&g_tick[lvl], 1u);
        CP_WAIT0;
        GBAR();
        t = tn; tn = sTick[grp]; buf ^= 1;
      }
    } else if (lvl == 4){
      // ---- static single wave per group ----
      int t = NGRP*(int)blockIdx.x + grp;
      if (t < tiles){
        stage16(gb0, Hsrc, tokens, symbols, lvl, t << 4, logm, m, total, ltid);
        CP_WAIT0;
        GBAR();
        float acc1[12][4], acc2[8][4];
        gemm_tile(sU, (const __half*)gb0, (const __half*)(gb0 + HL16), lane, 0, wn, acc1, acc2);
        epilogue_15(acc1, acc2, lvl, t << 4, off, m, logm, Csrc, Hdst, Cdst,
                    tokens, symbols, lane, 0, wn);
      }
    } else {
      // ---- lvl 5: static per group; results go straight into deep-phase smem ----
      int t = NGRP*(int)blockIdx.x + grp;
      const bool act = (t < tiles);
      float2 cnA[2][4];
      uint32_t hnA[2][4];
      if (act){
        stage16(gb0, Hsrc, tokens, symbols, lvl, t << 4, logm, m, total, ltid);
        CP_WAIT0;
        GBAR();
        float acc1[12][4], acc2[8][4];
        gemm_tile(sU, (const __half*)gb0, (const __half*)(gb0 + HL16), lane, 0, wn, acc1, acc2);
        #pragma unroll
        for (int half = 0; half < 2; half++){
          int nl = (lane >> 2) + 8*half;
          int n_g = (t << 4) + nl;
          int b = n_g >> logm, j = n_g & (m-1);
          int sym = __ldg(&symbols[b*(N_-1) + off + j]);
          int i0 = 2*n_g, i1 = 2*n_g + 1;
          const float2* cl2p = (const float2*)(Csrc + (size_t)i0*H_);
          const float2* cr2p = (const float2*)(Csrc + (size_t)i1*H_);
          const float4* tab  = (const float4*)(g_tab4 + sym*H_);
          const int e = 2*half;
          float2 cl[4], cr[4];
          #pragma unroll
          for (int s = 0; s < 4; s++){
            int c2 = 16*wn + 4*s + (lane & 3);
            cl[s] = ldcg2f(cl2p + c2);
            cr[s] = ldcg2f(cr2p + c2);
          }
          #pragma unroll
          for (int s = 0; s < 4; s++){
            int c2 = 16*wn + 4*s + (lane & 3);
            float4 t0 = __ldg(tab + 2*c2);
            float4 t1 = __ldg(tab + 2*c2 + 1);
            float2 cn, hn;
            gate2(acc1[0*4+s][e] + t0.x, acc1[0*4+s][e+1] + t1.x,
                  acc1[1*4+s][e] + t0.y, acc1[1*4+s][e+1] + t1.y,
                  acc1[2*4+s][e] + t0.z, acc1[2*4+s][e+1] + t1.z,
                  acc2[s][e]     + t0.w, acc2[s][e+1]     + t1.w,
                  acc2[4+s][e]   + t0.w, acc2[4+s][e+1]   + t1.w,
                  cl[s], cr[s], cn, hn);
            cnA[half][s] = cn;
            __half2 hh = __floats2half2_rn(hn.x, hn.y);
            hnA[half][s] = *reinterpret_cast<uint32_t*>(&hh);
          }
        }
      }
      __syncthreads();   // all groups done computing; group buffers free
      if (act){
        char* dpH = smx + SMU_BYTES + DP_H;
        char* dpC = smx + SMU_BYTES + DP_C;
        #pragma unroll
        for (int half = 0; half < 2; half++){
          int nl = (lane >> 2) + 8*half;
          int lr = 16*grp + nl;   // local row within this batch (t = 4*cta + grp)
          float2*  co = (float2*)(dpC + lr*512);
          uint32_t* ho = (uint32_t*)(dpH + lr*256);
          #pragma unroll
          for (int s = 0; s < 4; s++){
            int c2 = 16*wn + 4*s + (lane & 3);
            co[c2] = cnA[half][s];
            ho[c2] = hnA[half][s];
          }
        }
      }
      __syncthreads();
    }

    off += m; m >>= 1;
    if (lvl < 5) GRID_BAR();
  }

  // ---- deep phase: per-batch CTA, m = 32..1, all in smem (lvl5 data already here) ----
  if (blockIdx.x < B_){
    const int b = blockIdx.x;
    char* dpH = smx + SMU_BYTES + DP_H;
    char* dpC = smx + SMU_BYTES + DP_C;
    char* dpHL = smx + SMU_BYTES + DP_A;
    char* dpHR = dpHL + 8704;
    float* sRoot = (float*)(smx + SMU_BYTES + DP_ROOT);

    int offd = 4032;
    for (int dm = 32; dm >= 1; dm >>= 1){
      if (tid < dm*16){
        int r = tid >> 4, q = tid & 15;
        uint4 a  = *(const uint4*)(dpH + (2*r)*256 + q*16);
        uint4 b4 = *(const uint4*)(dpH + (2*r+1)*256 + q*16);
        int boff = r*(PADH*2) + q*16;
        *(uint4*)(dpHL + boff) = a;
        *(uint4*)(dpHR + boff) = b4;
      }
      __syncthreads();

      const int nrb = (dm + 15) >> 4;
      const bool part = (wmD < nrb);
      float acc1[12][4], acc2[8][4];
      if (part)
        gemm_tile(sU, (const __half*)dpHL, (const __half*)dpHR, lane, wmD, wn, acc1, acc2);

      float2 cpl[2][4], cpr[2][4];
      if (part){
        #pragma unroll
        for (int half = 0; half < 2; half++){
          int nl = 16*wmD + (lane >> 2) + 8*half;
          if (nl < dm){
            #pragma unroll
            for (int s = 0; s < 4; s++){
              int c2 = 16*wn + 4*s + (lane & 3);
              cpl[half][s] = ((const float2*)(dpC + (2*nl)*512))[c2];
              cpr[half][s] = ((const float2*)(dpC + (2*nl+1)*512))[c2];
            }
          }
        }
      }
      __syncthreads();

      if (part){
        #pragma unroll
        for (int half = 0; half < 2; half++){
          int nl = 16*wmD + (lane >> 2) + 8*half;
          if (nl >= dm) continue;
          int sym = __ldg(&symbols[b*(N_-1) + offd + nl]);
          const float4* tab = (const float4*)(g_tab4 + sym*H_);
          float2* co = (float2*)(dpC + nl*512);
          uint32_t* ho = (uint32_t*)(dpH + nl*256);
          const int e = 2*half;
          #pragma unroll
          for (int s = 0; s < 4; s++){
            int c2 = 16*wn + 4*s + (lane & 3);
            float4 t0 = __ldg(tab + 2*c2);
            float4 t1 = __ldg(tab + 2*c2 + 1);
            float2 cn, hn;
            gate2(acc1[0*4+s][e] + t0.x, acc1[0*4+s][e+1] + t1.x,
                  acc1[1*4+s][e] + t0.y, acc1[1*4+s][e+1] + t1.y,
                  acc1[2*4+s][e] + t0.z, acc1[2*4+s][e+1] + t1.z,
                  acc2[s][e]     + t0.w, acc2[s][e+1]     + t1.w,
                  acc2[4+s][e]   + t0.w, acc2[4+s][e+1]   + t1.w,
                  cpl[half][s], cpr[half][s], cn, hn);
            co[c2] = cn;
            __half2 hh = __floats2half2_rn(hn.x, hn.y);
            ho[c2] = *reinterpret_cast<uint32_t*>(&hh);
            if (dm == 1)
              ((float2*)sRoot)[c2] = hn;
          }
        }
      }
      __syncthreads();
      offd += dm;
    }

    // projection for this batch
    if (tid < H_){
      const int o = tid;
      float acc = bout[o];
      const float* w = Wout + o*H_;
      #pragma unroll 8
      for (int k = 0; k < H_; k++) acc += sRoot[k]*w[k];
      out[b*H_ + o] = acc;
    }
  }

  // ---- reset counters for next graph replay ----
  __syncthreads();
  if (tid == 0){
    unsigned d = atomicAdd(&g_done, 1u) + 1u;
    if (d == NCTAS){
      atomicExch(&g_bar, 0u);
      atomicExch(&g_done, 0u);
      #pragma unroll
      for (int i = 0; i < 4; i++) atomicExch(&g_tick[i], 0u);
    }
  }
}

// ---------------- host orchestration ----------------
extern "C" void kernel_launch(void* const* d_in, const int* in_sizes, int n_in,
                              void* d_out, int out_size) {
  const int*   tokens  = (const int*)  d_in[0];
  const int*   symbols = (const int*)  d_in[1];
  const float* emb     = (const float*)d_in[2];
  const float* sym_emb = (const float*)d_in[3];
  const float* Wp   = (const float*)d_in[4];
  const float* bp   = (const float*)d_in[5];
  const float* Wi   = (const float*)d_in[6];
  const float* bi   = (const float*)d_in[7];
  const float* Ui   = (const float*)d_in[8];
  const float* Wf   = (const float*)d_in[9];
  const float* bf   = (const float*)d_in[10];
  const float* Uf   = (const float*)d_in[11];
  const float* Wo   = (const float*)d_in[12];
  const float* bo   = (const float*)d_in[13];
  const float* Uo   = (const float*)d_in[14];
  const float* Wu   = (const float*)d_in[15];
  const float* bu   = (const float*)d_in[16];
  const float* Uu   = (const float*)d_in[17];
  const float* Wout = (const float*)d_in[18];
  const float* bout = (const float*)d_in[19];

  cudaFuncSetAttribute(fused_kernel, cudaFuncAttributeMaxDynamicSharedMemorySize, SM_TOTAL);
  fused_kernel<<<NCTAS, THREADS, SM_TOTAL>>>(
      tokens, symbols, emb, sym_emb, Wp, bp, Wi, bi, Ui, Wf, bf, Uf,
      Wo, bo, Uo, Wu, bu, Uu, Wout, bout, (float*)d_out);
}

// round 17
// speedup vs baseline: 1.0380x; 1.0380x over previous
#include <cuda_runtime.h>
#include <cuda_fp16.h>
#include <stdint.h>
#include <math.h>

#define B_ 64
#define N_ 4096
#define V_ 21
#define S_ 50
#define E_ 64
#define H_ 128
#define THREADS 512
#define GTHREADS 128
#define NGRP 4
#define NCTAS 148
#define PADH 136      // halves per padded smem row (272B)

#define NT0 22050     // 21*21*50 unique (tokL, tokR, symbol) leaf-pair triples
#define NPAIR 441     // 21*21 unique (tokL, tokR) pairs
#define PTILES 28     // ceil(441/16)

// smem layout (bytes)
#define SMU_BYTES (512*PADH*2)   // 139264: U-concat
#define HL16 4352                // 16 rows x 272B
#define BUF16 (2*HL16)           // 8704: HL+HR for one 16-row tile
#define SM_TOTAL (SMU_BYTES + NGRP*2*BUF16)   // 208896

// deep-phase layout inside the buffer region (offsets from SMU_BYTES)
#define DP_H    0        // 64 rows x 256B fp16
#define DP_C    16384    // 64 rows x 512B fp32
#define DP_A    49152    // HL 32x272 = 8704, HR 8704
#define DP_ROOT 66560    // 128 floats

// ---------------- static device scratch ----------------
__device__ float4 g_tab4[S_*H_];        // per-symbol gate tables: {ai, ao, au, af}
__device__ float4 g_P4[NPAIR*H_];       // per-pair preacts: {pi, po, pu, fl}
__device__ float  g_Pfr[NPAIR*H_];      // per-pair preacts: fr
__device__ __half g_h016[V_*H_];
__device__ float  g_c0[V_*H_];
__device__ __half g_Hm[22080*H_];       // memo: level-0 h by triple index
__device__ float  g_Cm[22080*H_];
__device__ __half g_HA[B_*1024*H_];     // lvl1,3 outputs
__device__ float  g_CA[B_*1024*H_];
__device__ __half g_HB[B_*512*H_];      // lvl2,4 outputs
__device__ float  g_CB[B_*512*H_];
__device__ unsigned g_tick[4];          // work-stealing counters lvl1..3
__device__ unsigned g_bar;
__device__ unsigned g_done;

__device__ __forceinline__ float tha(float x){
  float y; asm("tanh.approx.f32 %0, %1;" : "=f"(y) : "f"(x)); return y;
}
__device__ __forceinline__ float sga(float x){ return 0.5f*tha(0.5f*x) + 0.5f; }

__device__ __forceinline__ unsigned saddr(const void* p){
  return (unsigned)__cvta_generic_to_shared(p);
}
__device__ __forceinline__ void ldsm4(unsigned addr, unsigned &r0, unsigned &r1, unsigned &r2, unsigned &r3){
  asm volatile("ldmatrix.sync.aligned.m8n8.x4.shared.b16 {%0,%1,%2,%3}, [%4];"
    : "=r"(r0),"=r"(r1),"=r"(r2),"=r"(r3) : "r"(addr));
}
__device__ __forceinline__ void mma16816(float d[4], const unsigned a[4], unsigned b0, unsigned b1){
  asm volatile("mma.sync.aligned.m16n8k16.row.col.f32.f16.f16.f32 "
    "{%0,%1,%2,%3}, {%4,%5,%6,%7}, {%8,%9}, {%0,%1,%2,%3};"
    : "+f"(d[0]),"+f"(d[1]),"+f"(d[2]),"+f"(d[3])
    : "r"(a[0]),"r"(a[1]),"r"(a[2]),"r"(a[3]), "r"(b0),"r"(b1));
}
__device__ __forceinline__ uint32_t hadd2u(uint32_t a, uint32_t b){
  __half2 r = __hadd2(*reinterpret_cast<__half2*>(&a), *reinterpret_cast<__half2*>(&b));
  return *reinterpret_cast<uint32_t*>(&r);
}
__device__ __forceinline__ uint4 ldcg4(const uint4* p){
  uint4 v;
  asm volatile("ld.global.cg.v4.u32 {%0,%1,%2,%3}, [%4];"
    : "=r"(v.x),"=r"(v.y),"=r"(v.z),"=r"(v.w) : "l"(p));
  return v;
}
__device__ __forceinline__ float2 ldcg2f(const float2* p){
  float2 v;
  asm volatile("ld.global.cg.v2.f32 {%0,%1}, [%2];" : "=f"(v.x),"=f"(v.y) : "l"(p));
  return v;
}
__device__ __forceinline__ void stcg2f(float2* p, float2 v){
  asm volatile("st.global.cg.v2.f32 [%0], {%1,%2};" :: "l"(p), "f"(v.x), "f"(v.y) : "memory");
}
__device__ __forceinline__ void stcgu(uint32_t* p, uint32_t v){
  asm volatile("st.global.cg.u32 [%0], %1;" :: "l"(p), "r"(v) : "memory");
}
__device__ __forceinline__ void cpa16(uint32_t dst, const void* src){
  asm volatile("cp.async.cg.shared.global [%0], [%1], 16;" :: "r"(dst), "l"(src) : "memory");
}
#define CP_COMMIT asm volatile("cp.async.commit_group;" ::: "memory")
#define CP_WAIT0  asm volatile("cp.async.wait_group 0;" ::: "memory")

// memo index of leaf-pair node (b, jj) at the 2048-node level
__device__ __forceinline__ int memo_idx(const int* __restrict__ tokens,
                                        const int* __restrict__ symbols, int b, int jj){
  int ta = __ldg(&tokens[b*N_ + 2*jj]);
  int tb = __ldg(&tokens[b*N_ + 2*jj + 1]);
  int sy = __ldg(&symbols[b*(N_-1) + jj]);
  return (ta*V_ + tb)*S_ + sy;
}

// ---------------- GEMM tile: 16 (or 32 deep) rows x 128 cols, 5 gate-products ----------------
__device__ __forceinline__ void gemm_tile(const __half* sU, const __half* sHL, const __half* sHR,
                                          int lane, int wm, int wn,
                                          float acc1[12][4], float acc2[8][4]){
  #pragma unroll
  for (int i = 0; i < 12; i++){ acc1[i][0]=0.f; acc1[i][1]=0.f; acc1[i][2]=0.f; acc1[i][3]=0.f; }
  #pragma unroll
  for (int i = 0; i < 8; i++){ acc2[i][0]=0.f; acc2[i][1]=0.f; acc2[i][2]=0.f; acc2[i][3]=0.f; }
  #pragma unroll
  for (int k16 = 0; k16 < 8; k16++){
    const int kh = k16*16;
    const int arow = 16*wm + (lane & 15);
    const int acol = kh + (lane >> 4)*8;
    unsigned aL[4], aR[4], aT[4];
    ldsm4(saddr(&sHL[arow*PADH + acol]), aL[0],aL[1],aL[2],aL[3]);
    ldsm4(saddr(&sHR[arow*PADH + acol]), aR[0],aR[1],aR[2],aR[3]);
    #pragma unroll
    for (int i = 0; i < 4; i++) aT[i] = hadd2u(aL[i], aR[i]);   // ht = hl + hr

    const int brow_in = ((lane>>4)&1)*8 + (lane&7);
    const int bcol    = kh + ((lane>>3)&1)*8;
    #pragma unroll
    for (int gg = 0; gg < 3; gg++){
      #pragma unroll
      for (int sp = 0; sp < 2; sp++){
        int R0 = 128*gg + 32*wn + 16*sp;
        unsigned r0,r1,r2,r3;
        ldsm4(saddr(&sU[(R0 + brow_in)*PADH + bcol]), r0,r1,r2,r3);
        mma16816(acc1[gg*4 + 2*sp + 0], aT, r0, r1);
        mma16816(acc1[gg*4 + 2*sp + 1], aT, r2, r3);
      }
    }
    #pragma unroll
    for (int sp = 0; sp < 2; sp++){
      int R0 = 384 + 32*wn + 16*sp;
      unsigned r0,r1,r2,r3;
      ldsm4(saddr(&sU[(R0 + brow_in)*PADH + bcol]), r0,r1,r2,r3);
      mma16816(acc2[2*sp + 0], aL, r0, r1);
      mma16816(acc2[2*sp + 1], aL, r2, r3);
      mma16816(acc2[4 + 2*sp + 0], aR, r0, r1);
      mma16816(acc2[4 + 2*sp + 1], aR, r2, r3);
    }
  }
}

// async-stage 16-node tile. lvl==0: pair mode (i0 = p/21, i1 = p%21).
__device__ __forceinline__ void stage16(char* bufbase, const __half* Hsrc,
    const int* __restrict__ tokens, const int* __restrict__ symbols,
    int lvl, int node0, int logm, int m, int total, int ltid){
  const char* Hb = (const char*)Hsrc;
  uint32_t sHL = saddr(bufbase);
  uint32_t sHR = sHL + HL16;
  #pragma unroll
  for (int it = 0; it < 2; it++){
    int idx = ltid + it*GTHREADS;     // 0..255
    int r = idx >> 4, q = idx & 15;
    int n_g = node0 + r;
    int i0 = 0, i1 = 0;
    if (n_g < total){
      if (lvl == 0){
        i0 = n_g/V_;
        i1 = n_g - i0*V_;
      } else if (lvl == 1){
        int b = n_g >> logm, j = n_g & (m-1);
        i0 = memo_idx(tokens, symbols, b, 2*j);
        i1 = memo_idx(tokens, symbols, b, 2*j + 1);
      } else { i0 = 2*n_g; i1 = 2*n_g + 1; }
    }
    int boff = r*(PADH*2) + q*16;
    cpa16(sHL + boff, Hb + (size_t)i0*256 + q*16);
    cpa16(sHR + boff, Hb + (size_t)i1*256 + q*16);
  }
  CP_COMMIT;
}

// gate math for one column pair given fused table entries
__device__ __forceinline__ void gate2(
    float pi0, float pi1, float po0, float po1, float pu0, float pu1,
    float fl0, float fl1, float fr0, float fr1,
    float2 cl, float2 cr, float2 &cn, float2 &hn){
  cn.x = sga(pi0)*tha(pu0) + sga(fl0)*cl.x + sga(fr0)*cr.x;
  cn.y = sga(pi1)*tha(pu1) + sga(fl1)*cl.y + sga(fr1)*cr.y;
  hn.x = sga(po0)*tha(cn.x);
  hn.y = sga(po1)*tha(cn.y);
}

// epilogue for levels 1..4 (16-row tiles, wm = 0; all rows valid)
__device__ __forceinline__ void epilogue_15(
    const float acc1[12][4], const float acc2[8][4],
    int lvl, int node0, int off, int m, int logm,
    const float* Csrc, __half* Hdst, float* Cdst,
    const int* __restrict__ tokens, const int* __restrict__ symbols,
    int lane, int wm, int wn){
  #pragma unroll
  for (int half = 0; half < 2; half++){
    int nl = 16*wm + (lane >> 2) + 8*half;
    int n_g = node0 + nl;
    int b = n_g >> logm, j = n_g & (m-1);
    int sym = __ldg(&symbols[b*(N_-1) + off + j]);
    int i0, i1;
    if (lvl == 1){
      i0 = memo_idx(tokens, symbols, b, 2*j);
      i1 = memo_idx(tokens, symbols, b, 2*j + 1);
    } else { i0 = 2*n_g; i1 = 2*n_g + 1; }
    const float2* cl2p = (const float2*)(Csrc + (size_t)i0*H_);
    const float2* cr2p = (const float2*)(Csrc + (size_t)i1*H_);
    const float4* tab  = (const float4*)(g_tab4 + sym*H_);
    float2*  co = (float2*)(Cdst + (size_t)n_g*H_);
    uint32_t* ho = (uint32_t*)(Hdst + (size_t)n_g*H_);
    const int e = 2*half;
    float2 cl[4], cr[4];
    #pragma unroll
    for (int s = 0; s < 4; s++){
      int c2 = 16*wn + 4*s + (lane & 3);
      cl[s] = ldcg2f(cl2p + c2);
      cr[s] = ldcg2f(cr2p + c2);
    }
    #pragma unroll
    for (int s = 0; s < 4; s++){
      int c2 = 16*wn + 4*s + (lane & 3);
      float4 t0 = __ldg(tab + 2*c2);      // {ai, ao, au, af} col 2*c2
      float4 t1 = __ldg(tab + 2*c2 + 1);  // col 2*c2+1
      float2 cn, hn;
      gate2(acc1[0*4+s][e] + t0.x, acc1[0*4+s][e+1] + t1.x,
            acc1[1*4+s][e] + t0.y, acc1[1*4+s][e+1] + t1.y,
            acc1[2*4+s][e] + t0.z, acc1[2*4+s][e+1] + t1.z,
            acc2[s][e]     + t0.w, acc2[s][e+1]     + t1.w,
            acc2[4+s][e]   + t0.w, acc2[4+s][e+1]   + t1.w,
            cl[s], cr[s], cn, hn);
      stcg2f(co + c2, cn);
      __half2 hh = __floats2half2_rn(hn.x, hn.y);
      stcgu(ho + c2, *reinterpret_cast<uint32_t*>(&hh));
    }
  }
}

// ---------------- fused persistent kernel ----------------
extern __shared__ char smx[];
__global__ __launch_bounds__(THREADS, 1) void fused_kernel(
  const int* __restrict__ tokens, const int* __restrict__ symbols,
  const float* __restrict__ emb, const float* __restrict__ sym_emb,
  const float* __restrict__ Wp, const float* __restrict__ bp,
  const float* __restrict__ Wi, const float* __restrict__ bi,
  const float* __restrict__ Ui, const float* __restrict__ Wf,
  const float* __restrict__ bf, const float* __restrict__ Uf,
  const float* __restrict__ Wo, const float* __restrict__ bo,
  const float* __restrict__ Uo, const float* __restrict__ Wu,
  const float* __restrict__ bu, const float* __restrict__ Uu,
  const float* __restrict__ Wout, const float* __restrict__ bout,
  float* __restrict__ out)
{
  const int tid = threadIdx.x;
  const int lane = tid & 31, wid = tid >> 5;
  const int grp = tid >> 7;               // 0..3: independent quarter-CTA pipeline
  const int ltid = tid & 127;
  const int wn = wid & 3;                 // 32-col group
  const int wmD = wid >> 2;               // deep-phase row group (0..3)
  __half* sU = (__half*)smx;
  __shared__ int sTick[NGRP];

  #define GBAR() asm volatile("bar.sync %0, %1;" :: "r"(1 + grp), "r"(GTHREADS) : "memory")

  // ---- phase 0: stage fp16 U-concat into smem ----
  for (int idx = tid; idx < 512*32; idx += THREADS){
    int r = idx >> 5, q = idx & 31;
    const float* src = (r < 128) ? Ui + r*H_
                      : (r < 256) ? Uo + (r-128)*H_
                      : (r < 384) ? Uu + (r-256)*H_
                      :             Uf + (r-384)*H_;
    float4 v = __ldg((const float4*)src + q);
    __half2 h0 = __floats2half2_rn(v.x, v.y);
    __half2 h1 = __floats2half2_rn(v.z, v.w);
    uint2 u;
    u.x = *reinterpret_cast<uint32_t*>(&h0);
    u.y = *reinterpret_cast<uint32_t*>(&h1);
    *(uint2*)(smx + (r*PADH + q*4)*2) = u;
  }

  // ---- phase 0b: leaf/symbol tables ----
  if (blockIdx.x < V_ + S_){
    float* se = (float*)(smx + SMU_BYTES);
    float* sx = se + E_;
    const int v_or_s = blockIdx.x;
    const int h = tid;
    if (tid < E_)
      se[tid] = (v_or_s < V_) ? emb[v_or_s*E_ + tid] : sym_emb[(v_or_s - V_)*E_ + tid];
    __syncthreads();
    if (tid < H_){
      float x = bp[h];
      #pragma unroll 8
      for (int e = 0; e < E_; e++) x += se[e]*Wp[h*E_ + e];
      sx[h] = x;
    }
    __syncthreads();
    if (tid < H_){
      if (v_or_s < V_){
        float ai_ = bi[h], ao_ = bo[h], au_ = bu[h];
        #pragma unroll 8
        for (int k = 0; k < H_; k++){
          float xv = sx[k];
          ai_ += xv*Wi[h*H_+k]; ao_ += xv*Wo[h*H_+k]; au_ += xv*Wu[h*H_+k];
        }
        float gi = 1.f/(1.f+expf(-ai_)), go = 1.f/(1.f+expf(-ao_)), gu = tanhf(au_);
        float c = gi*gu;
        g_c0[v_or_s*H_+h] = c;
        g_h016[v_or_s*H_+h] = __float2half(go*tanhf(c));
      } else {
        int s = v_or_s - V_;
        float ai_ = bi[h], ao_ = bo[h], au_ = bu[h], af_ = bf[h];
        #pragma unroll 8
        for (int k = 0; k < H_; k++){
          float xv = sx[k];
          ai_ += xv*Wi[h*H_+k]; ao_ += xv*Wo[h*H_+k];
          au_ += xv*Wu[h*H_+k]; af_ += xv*Wf[h*H_+k];
        }
        g_tab4[s*H_+h] = make_float4(ai_, ao_, au_, af_);
      }
    }
  }

  unsigned ep = 0;
  #define GRID_BAR() do { \
    ep++; \
    __syncthreads(); \
    if (tid == 0){ \
      __threadfence(); \
      atomicAdd(&g_bar, 1u); \
      const unsigned tgt = ep*NCTAS; \
      while (*(volatile unsigned*)&g_bar < tgt) __nanosleep(32); \
      __threadfence(); \
    } \
    __syncthreads(); \
  } while(0)

  GRID_BAR();   // tables + U ready

  char* gb0 = smx + SMU_BYTES + grp*(2*BUF16);
  char* gb1 = gb0 + BUF16;

  // =========== phase P: pair preacts for 441 (tokL, tokR) pairs ===========
  {
    const int t = NGRP*(int)blockIdx.x + grp;
    if (t < PTILES){
      stage16(gb0, g_h016, tokens, symbols, 0, t << 4, 0, 0, NPAIR, ltid);
      CP_WAIT0;
      GBAR();
      float acc1[12][4], acc2[8][4];
      gemm_tile(sU, (const __half*)gb0, (const __half*)(gb0 + HL16), lane, 0, wn, acc1, acc2);
      #pragma unroll
      for (int half = 0; half < 2; half++){
        int nl = (lane >> 2) + 8*half;
        int p = (t << 4) + nl;
        if (p < NPAIR){
          const int e = 2*half;
          float4* P4 = g_P4 + (size_t)p*H_;
          float*  Pf = g_Pfr + (size_t)p*H_;
          #pragma unroll
          for (int s = 0; s < 4; s++){
            int c2 = 16*wn + 4*s + (lane & 3);
            P4[2*c2]   = make_float4(acc1[0*4+s][e],   acc1[1*4+s][e],   acc1[2*4+s][e],   acc2[s][e]);
            P4[2*c2+1] = make_float4(acc1[0*4+s][e+1], acc1[1*4+s][e+1], acc1[2*4+s][e+1], acc2[s][e+1]);
            Pf[2*c2]   = acc2[4+s][e];
            Pf[2*c2+1] = acc2[4+s][e+1];
          }
        }
      }
    }
  }
  GRID_BAR();

  // =========== phase M: memo elementwise over 22050 triples ===========
  {
    const float2* C02 = (const float2*)g_c0;
    for (int idx = (int)blockIdx.x*THREADS + tid; idx < NT0*64; idx += NCTAS*THREADS){
      int g = idx >> 6, cp = idx & 63;
      int ta = g/(V_*S_);
      int rem = g - ta*(V_*S_);
      int tb = rem/S_;
      int s  = rem - tb*S_;
      int pair = ta*V_ + tb;
      const float4* P4 = g_P4 + (size_t)pair*H_ + 2*cp;
      float4 a0 = __ldg(P4), a1 = __ldg(P4 + 1);
      float fr0 = __ldg(g_Pfr + (size_t)pair*H_ + 2*cp);
      float fr1 = __ldg(g_Pfr + (size_t)pair*H_ + 2*cp + 1);
      const float4* T4 = g_tab4 + (size_t)s*H_ + 2*cp;
      float4 t0 = __ldg(T4), t1 = __ldg(T4 + 1);
      float2 cl = __ldg(C02 + ta*64 + cp);
      float2 cr = __ldg(C02 + tb*64 + cp);
      float2 cn, hn;
      gate2(a0.x + t0.x, a1.x + t1.x,
            a0.y + t0.y, a1.y + t1.y,
            a0.z + t0.z, a1.z + t1.z,
            a0.w + t0.w, a1.w + t1.w,
            fr0 + t0.w,  fr1 + t1.w,
            cl, cr, cn, hn);
      stcg2f((float2*)g_Cm + (size_t)g*64 + cp, cn);
      __half2 hh = __floats2half2_rn(hn.x, hn.y);
      stcgu((uint32_t*)g_Hm + (size_t)g*64 + cp, *reinterpret_cast<uint32_t*>(&hh));
    }
  }
  GRID_BAR();

  // =========== levels 1..5 (m = 1024..64) ===========
  int m = 1024, off = 2048;
  for (int lvl = 1; lvl < 6; lvl++){
    const __half* Hsrc; const float* Csrc;
    __half* Hdst; float* Cdst;
    if (lvl == 1)      { Hsrc = g_Hm; Csrc = g_Cm; }
    else if (lvl & 1)  { Hsrc = g_HB; Csrc = g_CB; }
    else               { Hsrc = g_HA; Csrc = g_CA; }
    if (lvl & 1) { Hdst = g_HA; Cdst = g_CA; } else { Hdst = g_HB; Cdst = g_CB; }

    const int tiles = (B_*m) >> 4;
    const int logm  = 31 - __clz(m);
    const int total = B_*m;

    if (lvl <= 3){
      // ---- per-group work stealing ----
      if (ltid == 0) sTick[grp] = (int)atomicAdd(&g_tick[lvl], 1u);
      GBAR();
      int t = sTick[grp];
      int buf = 0;
      if (t < tiles)
        stage16(gb0, Hsrc, tokens, symbols, lvl, t << 4, logm, m, total, ltid);
      if (ltid == 0) sTick[grp] = (int)atomicAdd(&g_tick[lvl], 1u);
      CP_WAIT0;
      GBAR();
      int tn = sTick[grp];

      while (t < tiles){
        char* bb = buf ? gb1 : gb0;
        char* nb = buf ? gb0 : gb1;

        if (tn < tiles)
          stage16(nb, Hsrc, tokens, symbols, lvl, tn << 4, logm, m, total, ltid);

        float acc1[12][4], acc2[8][4];
        gemm_tile(sU, (const __half*)bb, (const __half*)(bb + HL16), lane, 0, wn, acc1, acc2);

        epilogue_15(acc1, acc2, lvl, t << 4, off, m, logm, Csrc, Hdst, Cdst,
                    tokens, symbols, lane, 0, wn);

        if (ltid == 0 && tn < tiles) sTick[grp] = (int)atomicAdd(&g_tick[lvl], 1u);
        CP_WAIT0;
        GBAR();
        t = tn; tn = sTick[grp]; buf ^= 1;
      }
    } else if (lvl == 4){
      // ---- static single wave per group ----
      int t = NGRP*(int)blockIdx.x + grp;
      if (t < tiles){
        stage16(gb0, Hsrc, tokens, symbols, lvl, t << 4, logm, m, total, ltid);
        CP_WAIT0;
        GBAR();
        float acc1[12][4], acc2[8][4];
        gemm_tile(sU, (const __half*)gb0, (const __half*)(gb0 + HL16), lane, 0, wn, acc1, acc2);
        epilogue_15(acc1, acc2, lvl, t << 4, off, m, logm, Csrc, Hdst, Cdst,
                    tokens, symbols, lane, 0, wn);
      }
    } else {
      // ---- lvl 5: static per group; results go straight into deep-phase smem ----
      int t = NGRP*(int)blockIdx.x + grp;
      const bool act = (t < tiles);
      float2 cnA[2][4];
      uint32_t hnA[2][4];
      if (act){
        stage16(gb0, Hsrc, tokens, symbols, lvl, t << 4, logm, m, total, ltid);
        CP_WAIT0;
        GBAR();
        float acc1[12][4], acc2[8][4];
        gemm_tile(sU, (const __half*)gb0, (const __half*)(gb0 + HL16), lane, 0, wn, acc1, acc2);
        #pragma unroll
        for (int half = 0; half < 2; half++){
          int nl = (lane >> 2) + 8*half;
          int n_g = (t << 4) + nl;
          int b = n_g >> logm, j = n_g & (m-1);
          int sym = __ldg(&symbols[b*(N_-1) + off + j]);
          int i0 = 2*n_g, i1 = 2*n_g + 1;
          const float2* cl2p = (const float2*)(Csrc + (size_t)i0*H_);
          const float2* cr2p = (const float2*)(Csrc + (size_t)i1*H_);
          const float4* tab  = (const float4*)(g_tab4 + sym*H_);
          const int e = 2*half;
          float2 cl[4], cr[4];
          #pragma unroll
          for (int s = 0; s < 4; s++){
            int c2 = 16*wn + 4*s + (lane & 3);
            cl[s] = ldcg2f(cl2p + c2);
            cr[s] = ldcg2f(cr2p + c2);
          }
          #pragma unroll
          for (int s = 0; s < 4; s++){
            int c2 = 16*wn + 4*s + (lane & 3);
            float4 t0 = __ldg(tab + 2*c2);
            float4 t1 = __ldg(tab + 2*c2 + 1);
            float2 cn, hn;
            gate2(acc1[0*4+s][e] + t0.x, acc1[0*4+s][e+1] + t1.x,
                  acc1[1*4+s][e] + t0.y, acc1[1*4+s][e+1] + t1.y,
                  acc1[2*4+s][e] + t0.z, acc1[2*4+s][e+1] + t1.z,
                  acc2[s][e]     + t0.w, acc2[s][e+1]     + t1.w,
                  acc2[4+s][e]   + t0.w, acc2[4+s][e+1]   + t1.w,
                  cl[s], cr[s], cn, hn);
            cnA[half][s] = cn;
            __half2 hh = __floats2half2_rn(hn.x, hn.y);
            hnA[half][s] = *reinterpret_cast<uint32_t*>(&hh);
          }
        }
      }
      __syncthreads();   // all groups done computing; group buffers free
      if (act){
        char* dpH = smx + SMU_BYTES + DP_H;
        char* dpC = smx + SMU_BYTES + DP_C;
        #pragma unroll
        for (int half = 0; half < 2; half++){
          int nl = (lane >> 2) + 8*half;
          int lr = 16*grp + nl;   // local row within this batch (t = 4*cta + grp)
          float2*  co = (float2*)(dpC + lr*512);
          uint32_t* ho = (uint32_t*)(dpH + lr*256);
          #pragma unroll
          for (int s = 0; s < 4; s++){
            int c2 = 16*wn + 4*s + (lane & 3);
            co[c2] = cnA[half][s];
            ho[c2] = hnA[half][s];
          }
        }
      }
      __syncthreads();
    }

    off += m; m >>= 1;
    if (lvl < 5) GRID_BAR();
  }

  // ---- deep phase: per-batch CTA, m = 32..1, all in smem (lvl5 data already here) ----
  if (blockIdx.x < B_){
    const int b = blockIdx.x;
    char* dpH = smx + SMU_BYTES + DP_H;
    char* dpC = smx + SMU_BYTES + DP_C;
    char* dpHL = smx + SMU_BYTES + DP_A;
    char* dpHR = dpHL + 8704;
    float* sRoot = (float*)(smx + SMU_BYTES + DP_ROOT);

    int offd = 4032;
    for (int dm = 32; dm >= 1; dm >>= 1){
      if (tid < dm*16){
        int r = tid >> 4, q = tid & 15;
        uint4 a  = *(const uint4*)(dpH + (2*r)*256 + q*16);
        uint4 b4 = *(const uint4*)(dpH + (2*r+1)*256 + q*16);
        int boff = r*(PADH*2) + q*16;
        *(uint4*)(dpHL + boff) = a;
        *(uint4*)(dpHR + boff) = b4;
      }
      __syncthreads();

      const int nrb = (dm + 15) >> 4;
      const bool part = (wmD < nrb);
      float acc1[12][4], acc2[8][4];
      if (part)
        gemm_tile(sU, (const __half*)dpHL, (const __half*)dpHR, lane, wmD, wn, acc1, acc2);

      float2 cpl[2][4], cpr[2][4];
      if (part){
        #pragma unroll
        for (int half = 0; half < 2; half++){
          int nl = 16*wmD + (lane >> 2) + 8*half;
          if (nl < dm){
            #pragma unroll
            for (int s = 0; s < 4; s++){
              int c2 = 16*wn + 4*s + (lane & 3);
              cpl[half][s] = ((const float2*)(dpC + (2*nl)*512))[c2];
              cpr[half][s] = ((const float2*)(dpC + (2*nl+1)*512))[c2];
            }
          }
        }
      }
      __syncthreads();

      if (part){
        #pragma unroll
        for (int half = 0; half < 2; half++){
          int nl = 16*wmD + (lane >> 2) + 8*half;
          if (nl >= dm) continue;
          int sym = __ldg(&symbols[b*(N_-1) + offd + nl]);
          const float4* tab = (const float4*)(g_tab4 + sym*H_);
          float2* co = (float2*)(dpC + nl*512);
          uint32_t* ho = (uint32_t*)(dpH + nl*256);
          const int e = 2*half;
          #pragma unroll
          for (int s = 0; s < 4; s++){
            int c2 = 16*wn + 4*s + (lane & 3);
            float4 t0 = __ldg(tab + 2*c2);
            float4 t1 = __ldg(tab + 2*c2 + 1);
            float2 cn, hn;
            gate2(acc1[0*4+s][e] + t0.x, acc1[0*4+s][e+1] + t1.x,
                  acc1[1*4+s][e] + t0.y, acc1[1*4+s][e+1] + t1.y,
                  acc1[2*4+s][e] + t0.z, acc1[2*4+s][e+1] + t1.z,
                  acc2[s][e]     + t0.w, acc2[s][e+1]     + t1.w,
                  acc2[4+s][e]   + t0.w, acc2[4+s][e+1]   + t1.w,
                  cpl[half][s], cpr[half][s], cn, hn);
            co[c2] = cn;
            __half2 hh = __floats2half2_rn(hn.x, hn.y);
            ho[c2] = *reinterpret_cast<uint32_t*>(&hh);
            if (dm == 1)
              ((float2*)sRoot)[c2] = hn;
          }
        }
      }
      __syncthreads();
      offd += dm;
    }

    // projection for this batch
    if (tid < H_){
      const int o = tid;
      float acc = bout[o];
      const float* w = Wout + o*H_;
      #pragma unroll 8
      for (int k = 0; k < H_; k++) acc += sRoot[k]*w[k];
      out[b*H_ + o] = acc;
    }
  }

  // ---- reset counters for next graph replay ----
  __syncthreads();
  if (tid == 0){
    unsigned d = atomicAdd(&g_done, 1u) + 1u;
    if (d == NCTAS){
      atomicExch(&g_bar, 0u);
      atomicExch(&g_done, 0u);
      #pragma unroll
      for (int i = 0; i < 4; i++) atomicExch(&g_tick[i], 0u);
    }
  }
}

// ---------------- host orchestration ----------------
extern "C" void kernel_launch(void* const* d_in, const int* in_sizes, int n_in,
                              void* d_out, int out_size) {
  const int*   tokens  = (const int*)  d_in[0];
  const int*   symbols = (const int*)  d_in[1];
  const float* emb     = (const float*)d_in[2];
  const float* sym_emb = (const float*)d_in[3];
  const float* Wp   = (const float*)d_in[4];
  const float* bp   = (const float*)d_in[5];
  const float* Wi   = (const float*)d_in[6];
  const float* bi   = (const float*)d_in[7];
  const float* Ui   = (const float*)d_in[8];
  const float* Wf   = (const float*)d_in[9];
  const float* bf   = (const float*)d_in[10];
  const float* Uf   = (const float*)d_in[11];
  const float* Wo   = (const float*)d_in[12];
  const float* bo   = (const float*)d_in[13];
  const float* Uo   = (const float*)d_in[14];
  const float* Wu   = (const float*)d_in[15];
  const float* bu   = (const float*)d_in[16];
  const float* Uu   = (const float*)d_in[17];
  const float* Wout = (const float*)d_in[18];
  const float* bout = (const float*)d_in[19];

  cudaFuncSetAttribute(fused_kernel, cudaFuncAttributeMaxDynamicSharedMemorySize, SM_TOTAL);
  fused_kernel<<<NCTAS, THREADS, SM_TOTAL>>>(
      tokens, symbols, emb, sym_emb, Wp, bp, Wi, bi, Ui, Wf, bf, Uf,
      Wo, bo, Uo, Wu, bu, Uu, Wout, bout, (float*)d_out);
}